// round 15
// baseline (speedup 1.0000x reference)
#include <cuda_runtime.h>
#include <cuda_fp16.h>
#include <cstdint>
#include <math.h>

#define N_B 32
#define T_S 2048
#define H_S 1024
#define D_S 384
#define ROWS (N_B * T_S)   // 65536

// scratch (no allocations allowed)
__device__ float g_cb[N_B * H_S];        // c_proj + bias
__device__ float g_scores[ROWS];
__device__ float g_weights[ROWS];
__device__ __half g_WhTH[H_S * H_S];     // WhT[c][k] = Wh[k][c], fp16
__device__ __half g_gruH[(size_t)ROWS * H_S];  // gru in fp16 (134 MB)
__device__ int g_flags[512];             // per-rowtile convert-done flags

// ---------------------------------------------------------------------------
// helpers
// ---------------------------------------------------------------------------
__device__ __forceinline__ uint32_t smem_u32(const void* p) {
    uint32_t a;
    asm("{ .reg .u64 t; cvta.to.shared.u64 t, %1; cvt.u32.u64 %0, t; }" : "=r"(a) : "l"(p));
    return a;
}
__device__ __forceinline__ float tanha(float x) {
    asm("tanh.approx.f32 %0, %0;" : "+f"(x));
    return x;
}
__device__ __forceinline__ void cp_async16(uint32_t dst, const void* src) {
    asm volatile("cp.async.cg.shared.global [%0], [%1], 16;" :: "r"(dst), "l"(src) : "memory");
}
__device__ __forceinline__ void ldmx4(uint32_t r[4], uint32_t addr) {
    asm volatile("ldmatrix.sync.aligned.m8n8.x4.shared.b16 {%0,%1,%2,%3}, [%4];"
                 : "=r"(r[0]), "=r"(r[1]), "=r"(r[2]), "=r"(r[3]) : "r"(addr));
}
__device__ __forceinline__ void mma16(float c[4], const uint32_t a[4], uint32_t b0, uint32_t b1) {
    asm volatile(
        "mma.sync.aligned.m16n8k16.row.col.f32.f16.f16.f32 "
        "{%0,%1,%2,%3}, {%4,%5,%6,%7}, {%8,%9}, {%0,%1,%2,%3};\n"
        : "+f"(c[0]), "+f"(c[1]), "+f"(c[2]), "+f"(c[3])
        : "r"(a[0]), "r"(a[1]), "r"(a[2]), "r"(a[3]), "r"(b0), "r"(b1));
}

// ---------------------------------------------------------------------------
// Launch 1: cb[n][k] = bias[k] + cond[n]·Wc[:,k]; zero scores, out, flags
// ---------------------------------------------------------------------------
__global__ void prep_kernel(const float* __restrict__ cond,
                            const float* __restrict__ Wc,
                            const float* __restrict__ bias,
                            float* __restrict__ out) {
    const int n = blockIdx.x;
    const int k = blockIdx.y * 256 + threadIdx.x;
    const int gid = (blockIdx.x * 4 + blockIdx.y) * 256 + threadIdx.x;
    if (gid < 512) g_flags[gid] = 0;
    float acc = bias[k];
    const float* cp = cond + n * D_S;
#pragma unroll 16
    for (int d = 0; d < D_S; d++)
        acc = fmaf(cp[d], Wc[d * H_S + k], acc);
    g_cb[n * H_S + k] = acc;
    out[n * H_S + k] = 0.0f;
    g_scores[n * T_S + blockIdx.y * 512 + threadIdx.x] = 0.0f;
    g_scores[n * T_S + blockIdx.y * 512 + threadIdx.x + 256] = 0.0f;
}

// ---------------------------------------------------------------------------
// Launch 2: transpose Wh -> g_WhTH (fp16). grid (32,32), block (32,8)
// ---------------------------------------------------------------------------
__global__ void transpose_wh(const float* __restrict__ Wh) {
    __shared__ float t[32][33];
    const int c0 = blockIdx.x * 32, k0 = blockIdx.y * 32;
    const int tx = threadIdx.x, ty = threadIdx.y;
#pragma unroll
    for (int i = 0; i < 4; i++)
        t[ty + 8 * i][tx] = Wh[(size_t)(k0 + ty + 8 * i) * H_S + c0 + tx];
    __syncthreads();
#pragma unroll
    for (int i = 0; i < 4; i++)
        g_WhTH[(size_t)(c0 + ty + 8 * i) * H_S + k0 + tx] = __float2half_rn(t[tx][ty + 8 * i]);
}

// ---------------------------------------------------------------------------
// Launch 3: fused converter + fp16 m16n8k16 GEMM + v·tanh epilogue.
// grid (9, 512): x==0 -> converter CTA for rowtile y (fp32->fp16, release
// flag); x in 1..8 -> GEMM CTA (col chunk x-1), acquire-spins on flag.
// GEMM: 128x128x1024/CTA, BK=64, 3-stage cp.async, 2 CTAs/SM, block 256.
// ---------------------------------------------------------------------------
#define BK 64
#define KT (H_S / BK)        // 16
#define RB 144               // smem row stride bytes (128B data + 16B pad)
#define A_BYTES (128 * RB)   // 18432
#define B_BYTES (128 * RB)   // 18432
#define STG_BYTES (A_BYTES + B_BYTES)  // 36864
#define NST 3
#define VCB_OFF (NST * STG_BYTES)      // 110592
#define SMEM_TOT (VCB_OFF + 128 * 8)   // 111616

__global__ __launch_bounds__(256, 2) void gemm_scores_mma(
    const float* __restrict__ gru, const float* __restrict__ v) {
    const int tid = threadIdx.x;
    const int ry = blockIdx.y;

    // ---------------- converter CTA ----------------
    if (blockIdx.x == 0) {
        const float* src = gru + (size_t)ry * 128 * H_S;
        __half* dst = g_gruH + (size_t)ry * 128 * H_S;
#pragma unroll 4
        for (int it = 0; it < 32; it++) {
            const size_t i = ((size_t)it * 256 + tid) * 16;
            const float4 x0 = *(const float4*)(src + i);
            const float4 x1 = *(const float4*)(src + i + 4);
            const float4 x2 = *(const float4*)(src + i + 8);
            const float4 x3 = *(const float4*)(src + i + 12);
            __half2 h[8];
            h[0] = __floats2half2_rn(x0.x, x0.y);
            h[1] = __floats2half2_rn(x0.z, x0.w);
            h[2] = __floats2half2_rn(x1.x, x1.y);
            h[3] = __floats2half2_rn(x1.z, x1.w);
            h[4] = __floats2half2_rn(x2.x, x2.y);
            h[5] = __floats2half2_rn(x2.z, x2.w);
            h[6] = __floats2half2_rn(x3.x, x3.y);
            h[7] = __floats2half2_rn(x3.z, x3.w);
            *(uint4*)(dst + i) = *(uint4*)h;
            *(uint4*)(dst + i + 8) = *(uint4*)(h + 4);
        }
        __syncthreads();
        if (tid == 0) {
            __threadfence();
            atomicExch(&g_flags[ry], 1);
        }
        return;
    }

    // ---------------- GEMM CTA ----------------
    extern __shared__ __align__(128) char smem[];
    const uint32_t sb = smem_u32(smem);
    float2* vcb = (float2*)(smem + VCB_OFF);

    const int wid = tid >> 5, lane = tid & 31;
    const int colBase = (blockIdx.x - 1) * 128;
    const int rowBase = ry * 128;
    const int n = rowBase >> 11;   // 128-row tiles never straddle a batch

    if (tid < 128)
        vcb[tid] = make_float2(v[colBase + tid], g_cb[n * H_S + colBase + tid]);

    // wait for this rowtile's fp16 A data
    if (tid == 0) {
        unsigned f;
        while (true) {
            asm volatile("ld.acquire.gpu.global.b32 %0, [%1];"
                         : "=r"(f) : "l"(&g_flags[ry]) : "memory");
            if (f) break;
            __nanosleep(128);
        }
    }
    __syncthreads();

    // --- gmem -> smem: per stage, A = 4 x 16B, B = 4 x 16B per thread
    const int lr = tid >> 3;          // row 0..31 (+32i)
    const int lcc = tid & 7;          // 16B chunk within 128B row
    const __half* srcA = g_gruH + (size_t)(rowBase + lr) * H_S + lcc * 8;
    const __half* srcB = g_WhTH + (size_t)(colBase + lr) * H_S + lcc * 8;
    const uint32_t dA = (uint32_t)(lr * RB + lcc * 16);

    // --- warp tile: rows 32*(wid&3), cols 64*(wid>>2)
    const int rows0 = (wid & 3) * 32;
    const int cols0 = (wid >> 2) * 64;
    const int sel = lane >> 3, j = lane & 7;
    const uint32_t aOff = (uint32_t)((rows0 + (sel & 1) * 8 + j) * RB + (sel >> 1) * 16);
    const uint32_t bOff = (uint32_t)((cols0 + (sel >> 1) * 8 + j) * RB + (sel & 1) * 16);

    float acc[2][8][4];
#pragma unroll
    for (int i = 0; i < 2; i++)
#pragma unroll
        for (int f = 0; f < 8; f++)
#pragma unroll
            for (int q = 0; q < 4; q++) acc[i][f][q] = 0.0f;

    auto issueA0 = [&](int s, int kc) {
        const uint32_t sa = sb + s * STG_BYTES;
        const __half* pa = srcA + kc * BK;
        cp_async16(sa + dA, pa);
        cp_async16(sa + dA + (32 * RB), pa + (size_t)32 * H_S);
    };
    auto issueA1 = [&](int s, int kc) {
        const uint32_t sa = sb + s * STG_BYTES;
        const __half* pa = srcA + kc * BK;
        cp_async16(sa + dA + 2 * (32 * RB), pa + (size_t)64 * H_S);
        cp_async16(sa + dA + 3 * (32 * RB), pa + (size_t)96 * H_S);
    };
    auto issueB0 = [&](int s, int kc) {
        const uint32_t sbb = sb + s * STG_BYTES + A_BYTES;
        const __half* pb = srcB + kc * BK;
        cp_async16(sbb + dA, pb);
        cp_async16(sbb + dA + (32 * RB), pb + (size_t)32 * H_S);
    };
    auto issueB1 = [&](int s, int kc) {
        const uint32_t sbb = sb + s * STG_BYTES + A_BYTES;
        const __half* pb = srcB + kc * BK;
        cp_async16(sbb + dA + 2 * (32 * RB), pb + (size_t)64 * H_S);
        cp_async16(sbb + dA + 3 * (32 * RB), pb + (size_t)96 * H_S);
        asm volatile("cp.async.commit_group;" ::: "memory");
    };

    issueA0(0, 0); issueA1(0, 0); issueB0(0, 0); issueB1(0, 0);
    issueA0(1, 1); issueA1(1, 1); issueB0(1, 1); issueB1(1, 1);

#pragma unroll 1
    for (int kc = 0; kc < KT; kc++) {
        if (kc + 1 < KT)
            asm volatile("cp.async.wait_group 1;" ::: "memory");
        else
            asm volatile("cp.async.wait_group 0;" ::: "memory");
        __syncthreads();

        const uint32_t base = sb + (kc % NST) * STG_BYTES;
        const uint32_t Ab = base + aOff;
        const uint32_t Bb = base + A_BYTES + bOff;
        const bool pre = (kc + 2 < KT);
        const int ps = (kc + 2) % NST;
        const int kc2 = kc + 2;

#pragma unroll
        for (int ks = 0; ks < 4; ks++) {   // 4 k-steps of 16 halves (32B each)
            uint32_t af[2][4], bf[4][4];
#pragma unroll
            for (int mf = 0; mf < 2; mf++)
                ldmx4(af[mf], Ab + mf * (16 * RB) + ks * 32);
#pragma unroll
            for (int nb = 0; nb < 4; nb++)
                ldmx4(bf[nb], Bb + nb * (16 * RB) + ks * 32);
#pragma unroll
            for (int nb = 0; nb < 4; nb++) {
                mma16(acc[0][2 * nb + 0], af[0], bf[nb][0], bf[nb][1]);
                mma16(acc[1][2 * nb + 0], af[1], bf[nb][0], bf[nb][1]);
                mma16(acc[0][2 * nb + 1], af[0], bf[nb][2], bf[nb][3]);
                mma16(acc[1][2 * nb + 1], af[1], bf[nb][2], bf[nb][3]);
            }
            if (pre) {
                if (ks == 0) issueA0(ps, kc2);
                else if (ks == 1) issueA1(ps, kc2);
                else if (ks == 2) issueB0(ps, kc2);
                else issueB1(ps, kc2);
            }
        }
    }

    // --- epilogue: partial score = sum_cols v[c] * tanh(hp + cb[c])
    float part[2][2] = {{0.0f, 0.0f}, {0.0f, 0.0f}};
#pragma unroll
    for (int mf = 0; mf < 2; mf++)
#pragma unroll
        for (int nf = 0; nf < 8; nf++) {
            const int c = cols0 + nf * 8 + 2 * (lane & 3);
            const float2 vc0 = vcb[c], vc1 = vcb[c + 1];
            part[mf][0] += vc0.x * tanha(acc[mf][nf][0] + vc0.y)
                         + vc1.x * tanha(acc[mf][nf][1] + vc1.y);
            part[mf][1] += vc0.x * tanha(acc[mf][nf][2] + vc0.y)
                         + vc1.x * tanha(acc[mf][nf][3] + vc1.y);
        }

#pragma unroll
    for (int mf = 0; mf < 2; mf++)
#pragma unroll
        for (int rh = 0; rh < 2; rh++) {
            float p = part[mf][rh];
            p += __shfl_xor_sync(0xffffffffu, p, 1);
            p += __shfl_xor_sync(0xffffffffu, p, 2);
            if ((lane & 3) == 0) {
                const int row = rowBase + rows0 + mf * 16 + rh * 8 + (lane >> 2);
                atomicAdd(&g_scores[row], p);
            }
        }
}

// ---------------------------------------------------------------------------
// Launch 4: softmax over T per batch. grid 32, block 1024
// ---------------------------------------------------------------------------
__global__ void softmax_kernel() {
    __shared__ float red[32];
    const int n = blockIdx.x, tid = threadIdx.x;
    const float s0 = g_scores[n * T_S + tid];
    const float s1 = g_scores[n * T_S + 1024 + tid];

    float m = fmaxf(s0, s1);
#pragma unroll
    for (int o = 16; o > 0; o >>= 1) m = fmaxf(m, __shfl_xor_sync(~0u, m, o));
    if ((tid & 31) == 0) red[tid >> 5] = m;
    __syncthreads();
    if (tid < 32) {
        float x = red[tid];
#pragma unroll
        for (int o = 16; o > 0; o >>= 1) x = fmaxf(x, __shfl_xor_sync(~0u, x, o));
        if (tid == 0) red[0] = x;
    }
    __syncthreads();
    const float M = red[0];
    __syncthreads();

    const float e0 = __expf(s0 - M), e1 = __expf(s1 - M);
    float s = e0 + e1;
#pragma unroll
    for (int o = 16; o > 0; o >>= 1) s += __shfl_xor_sync(~0u, s, o);
    if ((tid & 31) == 0) red[tid >> 5] = s;
    __syncthreads();
    if (tid < 32) {
        float x = red[tid];
#pragma unroll
        for (int o = 16; o > 0; o >>= 1) x += __shfl_xor_sync(~0u, x, o);
        if (tid == 0) red[0] = x;
    }
    __syncthreads();
    const float inv = 1.0f / red[0];
    g_weights[n * T_S + tid] = e0 * inv;
    g_weights[n * T_S + 1024 + tid] = e1 * inv;
}

// ---------------------------------------------------------------------------
// Launch 5: context[n,h] = sum_t w[n,t]*gruH[n,t,h] (fp16 reads, fp32 accum)
// grid (32, 16), block 128; 8 h-cols per thread, 128 t per chunk
// ---------------------------------------------------------------------------
__global__ void context_kernel(float* __restrict__ out) {
    __shared__ float sw[128];
    const int n = blockIdx.x, tc = blockIdx.y;
    const int tid = threadIdx.x;
    const int t0 = tc * 128;
    sw[tid] = g_weights[n * T_S + t0 + tid];
    __syncthreads();

    const int h = tid * 8;
    const __half* g = g_gruH + ((size_t)n * T_S + t0) * H_S + h;
    float acc[8] = {0.f, 0.f, 0.f, 0.f, 0.f, 0.f, 0.f, 0.f};
#pragma unroll 8
    for (int t = 0; t < 128; t++) {
        const uint4 raw = *(const uint4*)(g + (size_t)t * H_S);
        const __half2* hp = (const __half2*)&raw;
        const float w = sw[t];
#pragma unroll
        for (int q = 0; q < 4; q++) {
            const float2 f = __half22float2(hp[q]);
            acc[2 * q + 0] = fmaf(w, f.x, acc[2 * q + 0]);
            acc[2 * q + 1] = fmaf(w, f.y, acc[2 * q + 1]);
        }
    }
#pragma unroll
    for (int q = 0; q < 8; q++)
        atomicAdd(&out[n * H_S + h + q], acc[q]);
}

// ---------------------------------------------------------------------------
extern "C" void kernel_launch(void* const* d_in, const int* in_sizes, int n_in,
                              void* d_out, int out_size) {
    const float* gru  = (const float*)d_in[0];  // (32, 2048, 1024)
    const float* cond = (const float*)d_in[1];  // (32, 384)
    const float* Wh   = (const float*)d_in[2];  // (1024, 1024)
    const float* Wc   = (const float*)d_in[3];  // (384, 1024)
    const float* bias = (const float*)d_in[4];  // (1024,)
    const float* v    = (const float*)d_in[5];  // (1024,)
    float* out = (float*)d_out;                 // (32, 1024)

    static bool attr_done = false;
    if (!attr_done) {
        cudaFuncSetAttribute(gemm_scores_mma,
                             cudaFuncAttributeMaxDynamicSharedMemorySize, SMEM_TOT);
        attr_done = true;
    }

    prep_kernel<<<dim3(32, 4), 256>>>(cond, Wc, bias, out);
    transpose_wh<<<dim3(32, 32), dim3(32, 8)>>>(Wh);
    gemm_scores_mma<<<dim3(9, 512), 256, SMEM_TOT>>>(gru, v);
    softmax_kernel<<<32, 1024>>>();
    context_kernel<<<dim3(32, 16), 128>>>(out);
}

// round 16
// speedup vs baseline: 1.3631x; 1.3631x over previous
#include <cuda_runtime.h>
#include <cuda_fp16.h>
#include <cstdint>
#include <math.h>

#define N_B 32
#define T_S 2048
#define H_S 1024
#define D_S 384
#define ROWS (N_B * T_S)   // 65536

// scratch (no allocations allowed)
__device__ float g_cb[N_B * H_S];        // c_proj + bias
__device__ float g_scores[ROWS];
__device__ float g_weights[ROWS];
__device__ __half g_WhTH[H_S * H_S];     // WhT[c][k] = Wh[k][c], fp16
__device__ __half g_gruH[(size_t)ROWS * H_S];  // gru in fp16 (134 MB)

// ---------------------------------------------------------------------------
// helpers
// ---------------------------------------------------------------------------
__device__ __forceinline__ uint32_t smem_u32(const void* p) {
    uint32_t a;
    asm("{ .reg .u64 t; cvta.to.shared.u64 t, %1; cvt.u32.u64 %0, t; }" : "=r"(a) : "l"(p));
    return a;
}
__device__ __forceinline__ float tanha(float x) {
    asm("tanh.approx.f32 %0, %0;" : "+f"(x));
    return x;
}
__device__ __forceinline__ void cp_async16(uint32_t dst, const void* src) {
    asm volatile("cp.async.cg.shared.global [%0], [%1], 16;" :: "r"(dst), "l"(src) : "memory");
}
__device__ __forceinline__ void ldmx4(uint32_t r[4], uint32_t addr) {
    asm volatile("ldmatrix.sync.aligned.m8n8.x4.shared.b16 {%0,%1,%2,%3}, [%4];"
                 : "=r"(r[0]), "=r"(r[1]), "=r"(r[2]), "=r"(r[3]) : "r"(addr));
}
__device__ __forceinline__ void mma16(float c[4], const uint32_t a[4], uint32_t b0, uint32_t b1) {
    asm volatile(
        "mma.sync.aligned.m16n8k16.row.col.f32.f16.f16.f32 "
        "{%0,%1,%2,%3}, {%4,%5,%6,%7}, {%8,%9}, {%0,%1,%2,%3};\n"
        : "+f"(c[0]), "+f"(c[1]), "+f"(c[2]), "+f"(c[3])
        : "r"(a[0]), "r"(a[1]), "r"(a[2]), "r"(a[3]), "r"(b0), "r"(b1));
}

// ---------------------------------------------------------------------------
// Launch 0: convert gru fp32 -> fp16, streaming reads. grid 16384 x 256
// ---------------------------------------------------------------------------
__global__ void convert_gru_kernel(const float* __restrict__ g) {
    const size_t i = ((size_t)blockIdx.x * 256 + threadIdx.x) * 16;
    const float4 x0 = __ldcs((const float4*)(g + i));
    const float4 x1 = __ldcs((const float4*)(g + i + 4));
    const float4 x2 = __ldcs((const float4*)(g + i + 8));
    const float4 x3 = __ldcs((const float4*)(g + i + 12));
    __half2 h[8];
    h[0] = __floats2half2_rn(x0.x, x0.y);
    h[1] = __floats2half2_rn(x0.z, x0.w);
    h[2] = __floats2half2_rn(x1.x, x1.y);
    h[3] = __floats2half2_rn(x1.z, x1.w);
    h[4] = __floats2half2_rn(x2.x, x2.y);
    h[5] = __floats2half2_rn(x2.z, x2.w);
    h[6] = __floats2half2_rn(x3.x, x3.y);
    h[7] = __floats2half2_rn(x3.z, x3.w);
    *(uint4*)(g_gruH + i) = *(uint4*)h;
    *(uint4*)(g_gruH + i + 8) = *(uint4*)(h + 4);
}

// ---------------------------------------------------------------------------
// Launch 1 (merged): y<4 -> prep (cb, zero scores/out); y>=4 -> Wh transpose
// grid (32, 36), block 256
// ---------------------------------------------------------------------------
__global__ void prep_transpose_kernel(const float* __restrict__ cond,
                                      const float* __restrict__ Wc,
                                      const float* __restrict__ bias,
                                      const float* __restrict__ Wh,
                                      float* __restrict__ out) {
    const int tid = threadIdx.x;
    if (blockIdx.y < 4) {
        const int n = blockIdx.x;
        const int k = blockIdx.y * 256 + tid;
        float acc = bias[k];
        const float* cp = cond + n * D_S;
#pragma unroll 16
        for (int d = 0; d < D_S; d++)
            acc = fmaf(cp[d], Wc[d * H_S + k], acc);
        g_cb[n * H_S + k] = acc;
        out[n * H_S + k] = 0.0f;
        g_scores[n * T_S + blockIdx.y * 512 + tid] = 0.0f;
        g_scores[n * T_S + blockIdx.y * 512 + tid + 256] = 0.0f;
    } else {
        __shared__ float t[32][33];
        const int c0 = blockIdx.x * 32, k0 = (blockIdx.y - 4) * 32;
        const int tx = tid & 31, ty = tid >> 5;
#pragma unroll
        for (int i = 0; i < 4; i++)
            t[ty + 8 * i][tx] = Wh[(size_t)(k0 + ty + 8 * i) * H_S + c0 + tx];
        __syncthreads();
#pragma unroll
        for (int i = 0; i < 4; i++)
            g_WhTH[(size_t)(c0 + ty + 8 * i) * H_S + k0 + tx] =
                __float2half_rn(t[tx][ty + 8 * i]);
    }
}

// ---------------------------------------------------------------------------
// Launch 2: fp16 m16n8k16 GEMM 128x128x1024 per CTA + fused v·tanh epilogue
// BK=64, 3-stage cp.async (fine-grained issue spread), 2 CTAs/SM.
// grid (8 col-chunks, 512 row-tiles), block 256 (8 warps, 4x2 warp grid)
// ---------------------------------------------------------------------------
#define BK 64
#define KT (H_S / BK)        // 16
#define RB 144               // smem row stride bytes (128B data + 16B pad)
#define A_BYTES (128 * RB)   // 18432
#define B_BYTES (128 * RB)   // 18432
#define STG_BYTES (A_BYTES + B_BYTES)  // 36864
#define NST 3
#define VCB_OFF (NST * STG_BYTES)      // 110592
#define SMEM_TOT (VCB_OFF + 128 * 8)   // 111616

__global__ __launch_bounds__(256, 2) void gemm_scores_mma(
    const float* __restrict__ v) {
    extern __shared__ __align__(128) char smem[];
    const uint32_t sb = smem_u32(smem);
    float2* vcb = (float2*)(smem + VCB_OFF);

    const int tid = threadIdx.x, wid = tid >> 5, lane = tid & 31;
    const int colBase = blockIdx.x * 128;
    const int rowBase = blockIdx.y * 128;
    const int n = rowBase >> 11;   // 128-row tiles never straddle a batch

    if (tid < 128)
        vcb[tid] = make_float2(v[colBase + tid], g_cb[n * H_S + colBase + tid]);

    // --- gmem -> smem: per stage, A = 4 x 16B, B = 4 x 16B per thread
    const int lr = tid >> 3;          // row 0..31 (+32i)
    const int lcc = tid & 7;          // 16B chunk within 128B row
    const __half* srcA = g_gruH + (size_t)(rowBase + lr) * H_S + lcc * 8;
    const __half* srcB = g_WhTH + (size_t)(colBase + lr) * H_S + lcc * 8;
    const uint32_t dA = (uint32_t)(lr * RB + lcc * 16);

    // --- warp tile: rows 32*(wid&3), cols 64*(wid>>2)
    const int rows0 = (wid & 3) * 32;
    const int cols0 = (wid >> 2) * 64;
    const int sel = lane >> 3, j = lane & 7;
    const uint32_t aOff = (uint32_t)((rows0 + (sel & 1) * 8 + j) * RB + (sel >> 1) * 16);
    const uint32_t bOff = (uint32_t)((cols0 + (sel >> 1) * 8 + j) * RB + (sel & 1) * 16);

    float acc[2][8][4];
#pragma unroll
    for (int i = 0; i < 2; i++)
#pragma unroll
        for (int f = 0; f < 8; f++)
#pragma unroll
            for (int q = 0; q < 4; q++) acc[i][f][q] = 0.0f;

    // quarter-issues: 2 x 16B each; B1 also commits the group
    auto issueA0 = [&](int s, int kc) {
        const uint32_t sa = sb + s * STG_BYTES;
        const __half* pa = srcA + kc * BK;
        cp_async16(sa + dA, pa);
        cp_async16(sa + dA + (32 * RB), pa + (size_t)32 * H_S);
    };
    auto issueA1 = [&](int s, int kc) {
        const uint32_t sa = sb + s * STG_BYTES;
        const __half* pa = srcA + kc * BK;
        cp_async16(sa + dA + 2 * (32 * RB), pa + (size_t)64 * H_S);
        cp_async16(sa + dA + 3 * (32 * RB), pa + (size_t)96 * H_S);
    };
    auto issueB0 = [&](int s, int kc) {
        const uint32_t sbb = sb + s * STG_BYTES + A_BYTES;
        const __half* pb = srcB + kc * BK;
        cp_async16(sbb + dA, pb);
        cp_async16(sbb + dA + (32 * RB), pb + (size_t)32 * H_S);
    };
    auto issueB1 = [&](int s, int kc) {
        const uint32_t sbb = sb + s * STG_BYTES + A_BYTES;
        const __half* pb = srcB + kc * BK;
        cp_async16(sbb + dA + 2 * (32 * RB), pb + (size_t)64 * H_S);
        cp_async16(sbb + dA + 3 * (32 * RB), pb + (size_t)96 * H_S);
        asm volatile("cp.async.commit_group;" ::: "memory");
    };

    issueA0(0, 0); issueA1(0, 0); issueB0(0, 0); issueB1(0, 0);
    issueA0(1, 1); issueA1(1, 1); issueB0(1, 1); issueB1(1, 1);

#pragma unroll 1
    for (int kc = 0; kc < KT; kc++) {
        if (kc + 1 < KT)
            asm volatile("cp.async.wait_group 1;" ::: "memory");
        else
            asm volatile("cp.async.wait_group 0;" ::: "memory");
        __syncthreads();

        const uint32_t base = sb + (kc % NST) * STG_BYTES;
        const uint32_t Ab = base + aOff;
        const uint32_t Bb = base + A_BYTES + bOff;
        const bool pre = (kc + 2 < KT);
        const int ps = (kc + 2) % NST;
        const int kc2 = kc + 2;

#pragma unroll
        for (int ks = 0; ks < 4; ks++) {   // 4 k-steps of 16 halves (32B each)
            uint32_t af[2][4], bf[4][4];
#pragma unroll
            for (int mf = 0; mf < 2; mf++)
                ldmx4(af[mf], Ab + mf * (16 * RB) + ks * 32);
#pragma unroll
            for (int nb = 0; nb < 4; nb++)
                ldmx4(bf[nb], Bb + nb * (16 * RB) + ks * 32);
#pragma unroll
            for (int nb = 0; nb < 4; nb++) {
                mma16(acc[0][2 * nb + 0], af[0], bf[nb][0], bf[nb][1]);
                mma16(acc[1][2 * nb + 0], af[1], bf[nb][0], bf[nb][1]);
                mma16(acc[0][2 * nb + 1], af[0], bf[nb][2], bf[nb][3]);
                mma16(acc[1][2 * nb + 1], af[1], bf[nb][2], bf[nb][3]);
            }
            // spread next-stage loads across all four ks blocks
            if (pre) {
                if (ks == 0) issueA0(ps, kc2);
                else if (ks == 1) issueA1(ps, kc2);
                else if (ks == 2) issueB0(ps, kc2);
                else issueB1(ps, kc2);
            }
        }
    }

    // --- epilogue: partial score = sum_cols v[c] * tanh(hp + cb[c])
    float part[2][2] = {{0.0f, 0.0f}, {0.0f, 0.0f}};
#pragma unroll
    for (int mf = 0; mf < 2; mf++)
#pragma unroll
        for (int nf = 0; nf < 8; nf++) {
            const int c = cols0 + nf * 8 + 2 * (lane & 3);
            const float2 vc0 = vcb[c], vc1 = vcb[c + 1];
            part[mf][0] += vc0.x * tanha(acc[mf][nf][0] + vc0.y)
                         + vc1.x * tanha(acc[mf][nf][1] + vc1.y);
            part[mf][1] += vc0.x * tanha(acc[mf][nf][2] + vc0.y)
                         + vc1.x * tanha(acc[mf][nf][3] + vc1.y);
        }

#pragma unroll
    for (int mf = 0; mf < 2; mf++)
#pragma unroll
        for (int rh = 0; rh < 2; rh++) {
            float p = part[mf][rh];
            p += __shfl_xor_sync(0xffffffffu, p, 1);
            p += __shfl_xor_sync(0xffffffffu, p, 2);
            if ((lane & 3) == 0) {
                const int row = rowBase + rows0 + mf * 16 + rh * 8 + (lane >> 2);
                atomicAdd(&g_scores[row], p);
            }
        }
}

// ---------------------------------------------------------------------------
// Launch 3: softmax over T per batch. grid 32, block 1024
// ---------------------------------------------------------------------------
__global__ void softmax_kernel() {
    __shared__ float red[32];
    const int n = blockIdx.x, tid = threadIdx.x;
    const float s0 = g_scores[n * T_S + tid];
    const float s1 = g_scores[n * T_S + 1024 + tid];

    float m = fmaxf(s0, s1);
#pragma unroll
    for (int o = 16; o > 0; o >>= 1) m = fmaxf(m, __shfl_xor_sync(~0u, m, o));
    if ((tid & 31) == 0) red[tid >> 5] = m;
    __syncthreads();
    if (tid < 32) {
        float x = red[tid];
#pragma unroll
        for (int o = 16; o > 0; o >>= 1) x = fmaxf(x, __shfl_xor_sync(~0u, x, o));
        if (tid == 0) red[0] = x;
    }
    __syncthreads();
    const float M = red[0];
    __syncthreads();

    const float e0 = __expf(s0 - M), e1 = __expf(s1 - M);
    float s = e0 + e1;
#pragma unroll
    for (int o = 16; o > 0; o >>= 1) s += __shfl_xor_sync(~0u, s, o);
    if ((tid & 31) == 0) red[tid >> 5] = s;
    __syncthreads();
    if (tid < 32) {
        float x = red[tid];
#pragma unroll
        for (int o = 16; o > 0; o >>= 1) x += __shfl_xor_sync(~0u, x, o);
        if (tid == 0) red[0] = x;
    }
    __syncthreads();
    const float inv = 1.0f / red[0];
    g_weights[n * T_S + tid] = e0 * inv;
    g_weights[n * T_S + 1024 + tid] = e1 * inv;
}

// ---------------------------------------------------------------------------
// Launch 4: context[n,h] = sum_t w[n,t]*gruH[n,t,h] (fp16 reads, fp32 accum)
// grid (32, 16), block 128; 8 h-cols per thread, 128 t per chunk
// ---------------------------------------------------------------------------
__global__ void context_kernel(float* __restrict__ out) {
    __shared__ float sw[128];
    const int n = blockIdx.x, tc = blockIdx.y;
    const int tid = threadIdx.x;
    const int t0 = tc * 128;
    sw[tid] = g_weights[n * T_S + t0 + tid];
    __syncthreads();

    const int h = tid * 8;
    const __half* g = g_gruH + ((size_t)n * T_S + t0) * H_S + h;
    float acc[8] = {0.f, 0.f, 0.f, 0.f, 0.f, 0.f, 0.f, 0.f};
#pragma unroll 8
    for (int t = 0; t < 128; t++) {
        const uint4 raw = *(const uint4*)(g + (size_t)t * H_S);
        const __half2* hp = (const __half2*)&raw;
        const float w = sw[t];
#pragma unroll
        for (int q = 0; q < 4; q++) {
            const float2 f = __half22float2(hp[q]);
            acc[2 * q + 0] = fmaf(w, f.x, acc[2 * q + 0]);
            acc[2 * q + 1] = fmaf(w, f.y, acc[2 * q + 1]);
        }
    }
#pragma unroll
    for (int q = 0; q < 8; q++)
        atomicAdd(&out[n * H_S + h + q], acc[q]);
}

// ---------------------------------------------------------------------------
extern "C" void kernel_launch(void* const* d_in, const int* in_sizes, int n_in,
                              void* d_out, int out_size) {
    const float* gru  = (const float*)d_in[0];  // (32, 2048, 1024)
    const float* cond = (const float*)d_in[1];  // (32, 384)
    const float* Wh   = (const float*)d_in[2];  // (1024, 1024)
    const float* Wc   = (const float*)d_in[3];  // (384, 1024)
    const float* bias = (const float*)d_in[4];  // (1024,)
    const float* v    = (const float*)d_in[5];  // (1024,)
    float* out = (float*)d_out;                 // (32, 1024)

    static bool attr_done = false;
    if (!attr_done) {
        cudaFuncSetAttribute(gemm_scores_mma,
                             cudaFuncAttributeMaxDynamicSharedMemorySize, SMEM_TOT);
        attr_done = true;
    }

    convert_gru_kernel<<<16384, 256>>>(gru);
    prep_transpose_kernel<<<dim3(32, 36), 256>>>(cond, Wc, bias, Wh, out);
    gemm_scores_mma<<<dim3(8, 512), 256, SMEM_TOT>>>(v);
    softmax_kernel<<<32, 1024>>>();
    context_kernel<<<dim3(32, 16), 128>>>(out);
}

// round 17
// speedup vs baseline: 1.6677x; 1.2235x over previous
#include <cuda_runtime.h>
#include <cuda_fp16.h>
#include <cstdint>
#include <math.h>

#define N_B 32
#define T_S 2048
#define H_S 1024
#define D_S 384
#define ROWS (N_B * T_S)   // 65536

// scratch (no allocations allowed)
__device__ float g_cb[N_B * H_S];        // c_proj + bias
__device__ float g_scores[ROWS];
__device__ float g_weights[ROWS];
__device__ __half g_WhTH[H_S * H_S];     // WhT[c][k] = Wh[k][c], fp16
__device__ __half g_gruH[(size_t)ROWS * H_S];  // gru in fp16 (134 MB)

// ---------------------------------------------------------------------------
// helpers
// ---------------------------------------------------------------------------
__device__ __forceinline__ uint32_t smem_u32(const void* p) {
    uint32_t a;
    asm("{ .reg .u64 t; cvta.to.shared.u64 t, %1; cvt.u32.u64 %0, t; }" : "=r"(a) : "l"(p));
    return a;
}
__device__ __forceinline__ float tanha(float x) {
    asm("tanh.approx.f32 %0, %0;" : "+f"(x));
    return x;
}
__device__ __forceinline__ void cp_async16(uint32_t dst, const void* src) {
    asm volatile("cp.async.cg.shared.global [%0], [%1], 16;" :: "r"(dst), "l"(src) : "memory");
}
__device__ __forceinline__ void ldmx4(uint32_t r[4], uint32_t addr) {
    asm volatile("ldmatrix.sync.aligned.m8n8.x4.shared.b16 {%0,%1,%2,%3}, [%4];"
                 : "=r"(r[0]), "=r"(r[1]), "=r"(r[2]), "=r"(r[3]) : "r"(addr));
}
__device__ __forceinline__ void mma16(float c[4], const uint32_t a[4], uint32_t b0, uint32_t b1) {
    asm volatile(
        "mma.sync.aligned.m16n8k16.row.col.f32.f16.f16.f32 "
        "{%0,%1,%2,%3}, {%4,%5,%6,%7}, {%8,%9}, {%0,%1,%2,%3};\n"
        : "+f"(c[0]), "+f"(c[1]), "+f"(c[2]), "+f"(c[3])
        : "r"(a[0]), "r"(a[1]), "r"(a[2]), "r"(a[3]), "r"(b0), "r"(b1));
}

// ---------------------------------------------------------------------------
// Launch 0: convert gru fp32 -> fp16. 8 floats per thread. grid 32768 x 256
// (R11 configuration — measured inside the 424.0 champion total)
// ---------------------------------------------------------------------------
__global__ void convert_gru_kernel(const float* __restrict__ g) {
    const size_t i = ((size_t)blockIdx.x * 256 + threadIdx.x) * 8;
    const float4 x0 = *(const float4*)(g + i);
    const float4 x1 = *(const float4*)(g + i + 4);
    __half2 h[4];
    h[0] = __floats2half2_rn(x0.x, x0.y);
    h[1] = __floats2half2_rn(x0.z, x0.w);
    h[2] = __floats2half2_rn(x1.x, x1.y);
    h[3] = __floats2half2_rn(x1.z, x1.w);
    *(uint4*)(g_gruH + i) = *(uint4*)h;
}

// ---------------------------------------------------------------------------
// Launch 1: cb[n][k] = bias[k] + cond[n]·Wc[:,k]; zero scores, out
// ---------------------------------------------------------------------------
__global__ void prep_kernel(const float* __restrict__ cond,
                            const float* __restrict__ Wc,
                            const float* __restrict__ bias,
                            float* __restrict__ out) {
    const int n = blockIdx.x;
    const int k = blockIdx.y * 256 + threadIdx.x;
    float acc = bias[k];
    const float* cp = cond + n * D_S;
#pragma unroll 16
    for (int d = 0; d < D_S; d++)
        acc = fmaf(cp[d], Wc[d * H_S + k], acc);
    g_cb[n * H_S + k] = acc;
    out[n * H_S + k] = 0.0f;
    g_scores[n * T_S + blockIdx.y * 512 + threadIdx.x] = 0.0f;
    g_scores[n * T_S + blockIdx.y * 512 + threadIdx.x + 256] = 0.0f;
}

// ---------------------------------------------------------------------------
// Launch 2: transpose Wh -> g_WhTH (fp16). grid (32,32), block (32,8)
// ---------------------------------------------------------------------------
__global__ void transpose_wh(const float* __restrict__ Wh) {
    __shared__ float t[32][33];
    const int c0 = blockIdx.x * 32, k0 = blockIdx.y * 32;
    const int tx = threadIdx.x, ty = threadIdx.y;
#pragma unroll
    for (int i = 0; i < 4; i++)
        t[ty + 8 * i][tx] = Wh[(size_t)(k0 + ty + 8 * i) * H_S + c0 + tx];
    __syncthreads();
#pragma unroll
    for (int i = 0; i < 4; i++)
        g_WhTH[(size_t)(c0 + ty + 8 * i) * H_S + k0 + tx] = __float2half_rn(t[tx][ty + 8 * i]);
}

// ---------------------------------------------------------------------------
// Launch 3: fp16 m16n8k16 GEMM 128x128x1024 per CTA + fused v·tanh epilogue
// BK=64, 3-stage cp.async, quarter-granular issue spread (R14 GEMM: 305 us).
// grid (8 col-chunks, 512 row-tiles), block 256 (8 warps, 4x2), 2 CTAs/SM
// ---------------------------------------------------------------------------
#define BK 64
#define KT (H_S / BK)        // 16
#define RB 144               // smem row stride bytes (128B data + 16B pad)
#define A_BYTES (128 * RB)   // 18432
#define B_BYTES (128 * RB)   // 18432
#define STG_BYTES (A_BYTES + B_BYTES)  // 36864
#define NST 3
#define VCB_OFF (NST * STG_BYTES)      // 110592
#define SMEM_TOT (VCB_OFF + 128 * 8)   // 111616

__global__ __launch_bounds__(256, 2) void gemm_scores_mma(
    const float* __restrict__ v) {
    extern __shared__ __align__(128) char smem[];
    const uint32_t sb = smem_u32(smem);
    float2* vcb = (float2*)(smem + VCB_OFF);

    const int tid = threadIdx.x, wid = tid >> 5, lane = tid & 31;
    const int colBase = blockIdx.x * 128;
    const int rowBase = blockIdx.y * 128;
    const int n = rowBase >> 11;   // 128-row tiles never straddle a batch

    if (tid < 128)
        vcb[tid] = make_float2(v[colBase + tid], g_cb[n * H_S + colBase + tid]);

    // --- gmem -> smem: per stage, A = 4 x 16B, B = 4 x 16B per thread
    const int lr = tid >> 3;          // row 0..31 (+32i)
    const int lcc = tid & 7;          // 16B chunk within 128B row
    const __half* srcA = g_gruH + (size_t)(rowBase + lr) * H_S + lcc * 8;
    const __half* srcB = g_WhTH + (size_t)(colBase + lr) * H_S + lcc * 8;
    const uint32_t dA = (uint32_t)(lr * RB + lcc * 16);

    // --- warp tile: rows 32*(wid&3), cols 64*(wid>>2)
    const int rows0 = (wid & 3) * 32;
    const int cols0 = (wid >> 2) * 64;
    const int sel = lane >> 3, j = lane & 7;
    const uint32_t aOff = (uint32_t)((rows0 + (sel & 1) * 8 + j) * RB + (sel >> 1) * 16);
    const uint32_t bOff = (uint32_t)((cols0 + (sel >> 1) * 8 + j) * RB + (sel & 1) * 16);

    float acc[2][8][4];
#pragma unroll
    for (int i = 0; i < 2; i++)
#pragma unroll
        for (int f = 0; f < 8; f++)
#pragma unroll
            for (int q = 0; q < 4; q++) acc[i][f][q] = 0.0f;

    // quarter-issues: 2 x 16B each; B1 also commits the group
    auto issueA0 = [&](int s, int kc) {
        const uint32_t sa = sb + s * STG_BYTES;
        const __half* pa = srcA + kc * BK;
        cp_async16(sa + dA, pa);
        cp_async16(sa + dA + (32 * RB), pa + (size_t)32 * H_S);
    };
    auto issueA1 = [&](int s, int kc) {
        const uint32_t sa = sb + s * STG_BYTES;
        const __half* pa = srcA + kc * BK;
        cp_async16(sa + dA + 2 * (32 * RB), pa + (size_t)64 * H_S);
        cp_async16(sa + dA + 3 * (32 * RB), pa + (size_t)96 * H_S);
    };
    auto issueB0 = [&](int s, int kc) {
        const uint32_t sbb = sb + s * STG_BYTES + A_BYTES;
        const __half* pb = srcB + kc * BK;
        cp_async16(sbb + dA, pb);
        cp_async16(sbb + dA + (32 * RB), pb + (size_t)32 * H_S);
    };
    auto issueB1 = [&](int s, int kc) {
        const uint32_t sbb = sb + s * STG_BYTES + A_BYTES;
        const __half* pb = srcB + kc * BK;
        cp_async16(sbb + dA + 2 * (32 * RB), pb + (size_t)64 * H_S);
        cp_async16(sbb + dA + 3 * (32 * RB), pb + (size_t)96 * H_S);
        asm volatile("cp.async.commit_group;" ::: "memory");
    };

    issueA0(0, 0); issueA1(0, 0); issueB0(0, 0); issueB1(0, 0);
    issueA0(1, 1); issueA1(1, 1); issueB0(1, 1); issueB1(1, 1);

#pragma unroll 1
    for (int kc = 0; kc < KT; kc++) {
        if (kc + 1 < KT)
            asm volatile("cp.async.wait_group 1;" ::: "memory");
        else
            asm volatile("cp.async.wait_group 0;" ::: "memory");
        __syncthreads();

        const uint32_t base = sb + (kc % NST) * STG_BYTES;
        const uint32_t Ab = base + aOff;
        const uint32_t Bb = base + A_BYTES + bOff;
        const bool pre = (kc + 2 < KT);
        const int ps = (kc + 2) % NST;
        const int kc2 = kc + 2;

#pragma unroll
        for (int ks = 0; ks < 4; ks++) {   // 4 k-steps of 16 halves (32B each)
            uint32_t af[2][4], bf[4][4];
#pragma unroll
            for (int mf = 0; mf < 2; mf++)
                ldmx4(af[mf], Ab + mf * (16 * RB) + ks * 32);
#pragma unroll
            for (int nb = 0; nb < 4; nb++)
                ldmx4(bf[nb], Bb + nb * (16 * RB) + ks * 32);
#pragma unroll
            for (int nb = 0; nb < 4; nb++) {
                mma16(acc[0][2 * nb + 0], af[0], bf[nb][0], bf[nb][1]);
                mma16(acc[1][2 * nb + 0], af[1], bf[nb][0], bf[nb][1]);
                mma16(acc[0][2 * nb + 1], af[0], bf[nb][2], bf[nb][3]);
                mma16(acc[1][2 * nb + 1], af[1], bf[nb][2], bf[nb][3]);
            }
            // spread next-stage loads across all four ks blocks
            if (pre) {
                if (ks == 0) issueA0(ps, kc2);
                else if (ks == 1) issueA1(ps, kc2);
                else if (ks == 2) issueB0(ps, kc2);
                else issueB1(ps, kc2);
            }
        }
    }

    // --- epilogue: partial score = sum_cols v[c] * tanh(hp + cb[c])
    float part[2][2] = {{0.0f, 0.0f}, {0.0f, 0.0f}};
#pragma unroll
    for (int mf = 0; mf < 2; mf++)
#pragma unroll
        for (int nf = 0; nf < 8; nf++) {
            const int c = cols0 + nf * 8 + 2 * (lane & 3);
            const float2 vc0 = vcb[c], vc1 = vcb[c + 1];
            part[mf][0] += vc0.x * tanha(acc[mf][nf][0] + vc0.y)
                         + vc1.x * tanha(acc[mf][nf][1] + vc1.y);
            part[mf][1] += vc0.x * tanha(acc[mf][nf][2] + vc0.y)
                         + vc1.x * tanha(acc[mf][nf][3] + vc1.y);
        }

#pragma unroll
    for (int mf = 0; mf < 2; mf++)
#pragma unroll
        for (int rh = 0; rh < 2; rh++) {
            float p = part[mf][rh];
            p += __shfl_xor_sync(0xffffffffu, p, 1);
            p += __shfl_xor_sync(0xffffffffu, p, 2);
            if ((lane & 3) == 0) {
                const int row = rowBase + rows0 + mf * 16 + rh * 8 + (lane >> 2);
                atomicAdd(&g_scores[row], p);
            }
        }
}

// ---------------------------------------------------------------------------
// Launch 4: softmax over T per batch. grid 32, block 1024
// ---------------------------------------------------------------------------
__global__ void softmax_kernel() {
    __shared__ float red[32];
    const int n = blockIdx.x, tid = threadIdx.x;
    const float s0 = g_scores[n * T_S + tid];
    const float s1 = g_scores[n * T_S + 1024 + tid];

    float m = fmaxf(s0, s1);
#pragma unroll
    for (int o = 16; o > 0; o >>= 1) m = fmaxf(m, __shfl_xor_sync(~0u, m, o));
    if ((tid & 31) == 0) red[tid >> 5] = m;
    __syncthreads();
    if (tid < 32) {
        float x = red[tid];
#pragma unroll
        for (int o = 16; o > 0; o >>= 1) x = fmaxf(x, __shfl_xor_sync(~0u, x, o));
        if (tid == 0) red[0] = x;
    }
    __syncthreads();
    const float M = red[0];
    __syncthreads();

    const float e0 = __expf(s0 - M), e1 = __expf(s1 - M);
    float s = e0 + e1;
#pragma unroll
    for (int o = 16; o > 0; o >>= 1) s += __shfl_xor_sync(~0u, s, o);
    if ((tid & 31) == 0) red[tid >> 5] = s;
    __syncthreads();
    if (tid < 32) {
        float x = red[tid];
#pragma unroll
        for (int o = 16; o > 0; o >>= 1) x += __shfl_xor_sync(~0u, x, o);
        if (tid == 0) red[0] = x;
    }
    __syncthreads();
    const float inv = 1.0f / red[0];
    g_weights[n * T_S + tid] = e0 * inv;
    g_weights[n * T_S + 1024 + tid] = e1 * inv;
}

// ---------------------------------------------------------------------------
// Launch 5: context[n,h] = sum_t w[n,t]*gruH[n,t,h] (fp16 reads, fp32 accum)
// grid (32, 16), block 128; 8 h-cols per thread, 128 t per chunk
// ---------------------------------------------------------------------------
__global__ void context_kernel(float* __restrict__ out) {
    __shared__ float sw[128];
    const int n = blockIdx.x, tc = blockIdx.y;
    const int tid = threadIdx.x;
    const int t0 = tc * 128;
    sw[tid] = g_weights[n * T_S + t0 + tid];
    __syncthreads();

    const int h = tid * 8;
    const __half* g = g_gruH + ((size_t)n * T_S + t0) * H_S + h;
    float acc[8] = {0.f, 0.f, 0.f, 0.f, 0.f, 0.f, 0.f, 0.f};
#pragma unroll 8
    for (int t = 0; t < 128; t++) {
        const uint4 raw = *(const uint4*)(g + (size_t)t * H_S);
        const __half2* hp = (const __half2*)&raw;
        const float w = sw[t];
#pragma unroll
        for (int q = 0; q < 4; q++) {
            const float2 f = __half22float2(hp[q]);
            acc[2 * q + 0] = fmaf(w, f.x, acc[2 * q + 0]);
            acc[2 * q + 1] = fmaf(w, f.y, acc[2 * q + 1]);
        }
    }
#pragma unroll
    for (int q = 0; q < 8; q++)
        atomicAdd(&out[n * H_S + h + q], acc[q]);
}

// ---------------------------------------------------------------------------
extern "C" void kernel_launch(void* const* d_in, const int* in_sizes, int n_in,
                              void* d_out, int out_size) {
    const float* gru  = (const float*)d_in[0];  // (32, 2048, 1024)
    const float* cond = (const float*)d_in[1];  // (32, 384)
    const float* Wh   = (const float*)d_in[2];  // (1024, 1024)
    const float* Wc   = (const float*)d_in[3];  // (384, 1024)
    const float* bias = (const float*)d_in[4];  // (1024,)
    const float* v    = (const float*)d_in[5];  // (1024,)
    float* out = (float*)d_out;                 // (32, 1024)

    static bool attr_done = false;
    if (!attr_done) {
        cudaFuncSetAttribute(gemm_scores_mma,
                             cudaFuncAttributeMaxDynamicSharedMemorySize, SMEM_TOT);
        attr_done = true;
    }

    convert_gru_kernel<<<32768, 256>>>(gru);
    prep_kernel<<<dim3(32, 4), 256>>>(cond, Wc, bias, out);
    transpose_wh<<<dim3(32, 32), dim3(32, 8)>>>(Wh);
    gemm_scores_mma<<<dim3(8, 512), 256, SMEM_TOT>>>(v);
    softmax_kernel<<<32, 1024>>>();
    context_kernel<<<dim3(32, 16), 128>>>(out);
}